// round 4
// baseline (speedup 1.0000x reference)
#include <cuda_runtime.h>
#include <cuda_bf16.h>

// NuclearLossFunc: loss = sum(x^2) / (B*C), x: (32,64,256,256) fp32
// = 134,217,728 elements = 512 MiB read. Pure HBM-bound reduction.
//
// R4: R1 hot loop (proven ~7 TB/s) + last-block-done finalize, but the
// election uses atom.add.acq_rel.gpu (release orders the same-thread
// partial store; acquire orders the last block's reads) instead of
// __threadfence()+atomicAdd — avoids MEMBAR.GPU + CCTL.IVALL L1-flush
// per block, which is the suspected ~7us epilogue tax in R3.
// Streaming loads use __ldcs (no reuse -> evict-first).

#define NBLOCKS 1184           // 148 SMs * 8 CTAs
#define NTHREADS 512

__device__ float        g_partials[NBLOCKS];
__device__ unsigned int g_count;   // zero-initialized at module load

__global__ __launch_bounds__(NTHREADS) void sqsum_fused_kernel(
    const float4* __restrict__ in, int n4,
    float* __restrict__ out, float scale)
{
    const int lane = threadIdx.x & 31;
    const int wid  = threadIdx.x >> 5;
    __shared__ float ws[NTHREADS / 32];
    __shared__ bool  s_is_last;

    // ---- hot loop: R1 structure, streaming loads, 32-bit indexing ----
    float s0 = 0.f, s1 = 0.f, s2 = 0.f, s3 = 0.f;
    int idx    = blockIdx.x * NTHREADS + threadIdx.x;
    int stride = gridDim.x * NTHREADS;

    for (int i = idx; i < n4; i += stride) {
        float4 v = __ldcs(in + i);
        s0 = fmaf(v.x, v.x, s0);
        s1 = fmaf(v.y, v.y, s1);
        s2 = fmaf(v.z, v.z, s2);
        s3 = fmaf(v.w, v.w, s3);
    }
    float s = (s0 + s1) + (s2 + s3);

    #pragma unroll
    for (int o = 16; o > 0; o >>= 1)
        s += __shfl_xor_sync(0xffffffffu, s, o);

    if (lane == 0) ws[wid] = s;
    __syncthreads();

    if (wid == 0) {
        s = (lane < NTHREADS / 32) ? ws[lane] : 0.f;
        #pragma unroll
        for (int o = 16; o > 0; o >>= 1)
            s += __shfl_xor_sync(0xffffffffu, s, o);
        if (lane == 0) g_partials[blockIdx.x] = s;   // same thread releases below
    }

    // ---- last-block election: single acq_rel atomic, no MEMBAR/L1-flush ----
    if (threadIdx.x == 0) {
        unsigned int ticket;
        asm volatile("atom.add.acq_rel.gpu.u32 %0, [%1], 1;"
                     : "=r"(ticket) : "l"(&g_count) : "memory");
        s_is_last = (ticket == (unsigned int)(gridDim.x - 1));
    }
    __syncthreads();
    if (!s_is_last) return;

    // ---- last block: reduce partials in double (deterministic) ----
    __shared__ double wd[NTHREADS / 32];
    double d = 0.0;
    for (int p = threadIdx.x; p < NBLOCKS; p += NTHREADS)
        d += (double)g_partials[p];

    #pragma unroll
    for (int o = 16; o > 0; o >>= 1)
        d += __shfl_xor_sync(0xffffffffu, d, o);

    if (lane == 0) wd[wid] = d;
    __syncthreads();

    if (wid == 0) {
        d = (lane < NTHREADS / 32) ? wd[lane] : 0.0;
        #pragma unroll
        for (int o = 16; o > 0; o >>= 1)
            d += __shfl_xor_sync(0xffffffffu, d, o);
        if (lane == 0) {
            out[0] = (float)(d * (double)scale);
            g_count = 0;  // reset for graph replay (visible at kernel boundary)
        }
    }
}

extern "C" void kernel_launch(void* const* d_in, const int* in_sizes, int n_in,
                              void* d_out, int out_size)
{
    const float* x = (const float*)d_in[0];
    long long n = (long long)in_sizes[0];     // 134217728, divisible by 4
    int n4 = (int)(n >> 2);                   // 33,554,432 fits in int

    // B*C = n / (256*256) = 2048
    float scale = 1.0f / (float)(n / (256LL * 256LL));

    sqsum_fused_kernel<<<NBLOCKS, NTHREADS>>>((const float4*)x, n4,
                                              (float*)d_out, scale);
}

// round 5
// speedup vs baseline: 1.0806x; 1.0806x over previous
#include <cuda_runtime.h>
#include <cuda_bf16.h>

// NuclearLossFunc: loss = sum(x^2) / (B*C), x: (32,64,256,256) fp32
// = 134,217,728 elements = 512 MiB read. Pure HBM-bound reduction.
//
// R5: exact R1 pass-1 (the 7.06 TB/s record loop: long long indexing,
// plain float4 loads, 1184x512) + finalize overlapped via PDL
// (programmatic dependent launch). Pass-1 signals launch_dependents
// after storing its partial; finalize launches early, then
// griddepcontrol.wait blocks until pass-1 completes with memory
// visibility. Deterministic: fixed reduction tree in double.

#define NBLOCKS 1184           // 148 SMs * 8 CTAs
#define NTHREADS 512
#define FTHREADS 128

__device__ float g_partials[NBLOCKS];

__global__ __launch_bounds__(NTHREADS) void sqsum_kernel(
    const float4* __restrict__ in, long long n4)
{
    float s0 = 0.f, s1 = 0.f, s2 = 0.f, s3 = 0.f;
    long long idx    = (long long)blockIdx.x * blockDim.x + threadIdx.x;
    long long stride = (long long)gridDim.x * blockDim.x;

    for (long long i = idx; i < n4; i += stride) {
        float4 v = in[i];
        s0 = fmaf(v.x, v.x, s0);
        s1 = fmaf(v.y, v.y, s1);
        s2 = fmaf(v.z, v.z, s2);
        s3 = fmaf(v.w, v.w, s3);
    }
    float s = (s0 + s1) + (s2 + s3);

    #pragma unroll
    for (int o = 16; o > 0; o >>= 1)
        s += __shfl_xor_sync(0xffffffffu, s, o);

    __shared__ float ws[NTHREADS / 32];
    int lane = threadIdx.x & 31;
    int wid  = threadIdx.x >> 5;
    if (lane == 0) ws[wid] = s;
    __syncthreads();

    if (wid == 0) {
        s = (lane < NTHREADS / 32) ? ws[lane] : 0.f;
        #pragma unroll
        for (int o = 16; o > 0; o >>= 1)
            s += __shfl_xor_sync(0xffffffffu, s, o);
        if (lane == 0) g_partials[blockIdx.x] = s;
    }

    // Allow the dependent (finalize) grid to begin launching while this
    // grid drains. Memory visibility is enforced by griddepcontrol.wait
    // on the consumer side, not by this trigger.
    asm volatile("griddepcontrol.launch_dependents;");
}

__global__ __launch_bounds__(FTHREADS) void finalize_kernel(
    float* __restrict__ out, int nblocks, float scale)
{
    // Launched early under PDL: CTA setup overlaps pass-1 drain.
    // Wait for pass-1 completion + memory visibility.
    asm volatile("griddepcontrol.wait;");

    double s = 0.0;
    for (int i = threadIdx.x; i < nblocks; i += FTHREADS)
        s += (double)g_partials[i];

    #pragma unroll
    for (int o = 16; o > 0; o >>= 1)
        s += __shfl_xor_sync(0xffffffffu, s, o);

    __shared__ double ws[FTHREADS / 32];
    int lane = threadIdx.x & 31;
    int wid  = threadIdx.x >> 5;
    if (lane == 0) ws[wid] = s;
    __syncthreads();

    if (wid == 0) {
        s = (lane < FTHREADS / 32) ? ws[lane] : 0.0;
        #pragma unroll
        for (int o = 16; o > 0; o >>= 1)
            s += __shfl_xor_sync(0xffffffffu, s, o);
        if (lane == 0) out[0] = (float)(s * (double)scale);
    }
}

extern "C" void kernel_launch(void* const* d_in, const int* in_sizes, int n_in,
                              void* d_out, int out_size)
{
    const float* x = (const float*)d_in[0];
    long long n = (long long)in_sizes[0];     // 134217728, divisible by 4
    long long n4 = n >> 2;

    // B*C = n / (256*256) = 2048
    float scale = 1.0f / (float)(n / (256LL * 256LL));

    sqsum_kernel<<<NBLOCKS, NTHREADS>>>((const float4*)x, n4);

    // Finalize with programmatic dependent launch: overlaps its grid
    // launch/setup with pass-1's drain phase.
    cudaLaunchConfig_t cfg = {};
    cfg.gridDim  = dim3(1, 1, 1);
    cfg.blockDim = dim3(FTHREADS, 1, 1);
    cfg.dynamicSmemBytes = 0;
    cfg.stream = 0;  // same (capture) stream as pass-1

    cudaLaunchAttribute attr[1];
    attr[0].id = cudaLaunchAttributeProgrammaticStreamSerialization;
    attr[0].val.programmaticStreamSerializationAllowed = 1;
    cfg.attrs = attr;
    cfg.numAttrs = 1;

    cudaLaunchKernelEx(&cfg, finalize_kernel, (float*)d_out, (int)NBLOCKS, scale);
}

// round 6
// speedup vs baseline: 1.0831x; 1.0023x over previous
#include <cuda_runtime.h>
#include <cuda_bf16.h>

// NuclearLossFunc: loss = sum(x^2) / (B*C), x: (32,64,256,256) fp32
// = 134,217,728 elements = 512 MiB read. Pure HBM-bound reduction.
//
// R6: fused single kernel, single wave (148 SMs x 4 CTAs x 512 thr =
// 592 CTAs, 2048 thr/SM). Hot loop is verbatim the R1/R5 loop that
// twice measured ~7.05-7.1 TB/s. Last-block-done election via one
// atom.add.acq_rel.gpu (release: same-thread partial store; acquire:
// last block's partial reads) — no MEMBAR.GPU, no CCTL.IVALL L1 flush.
// Deterministic: fixed reduction tree, final accumulate in double.

#define NBLOCKS 592            // 148 SMs * 4 CTAs -> exactly one wave
#define NTHREADS 512

__device__ float        g_partials[NBLOCKS];
__device__ unsigned int g_count;   // zero-initialized at module load

__global__ __launch_bounds__(NTHREADS) void sqsum_fused_kernel(
    const float4* __restrict__ in, long long n4,
    float* __restrict__ out, float scale)
{
    const int lane = threadIdx.x & 31;
    const int wid  = threadIdx.x >> 5;
    __shared__ float ws[NTHREADS / 32];
    __shared__ bool  s_is_last;

    // ---- hot loop: DO NOT TOUCH (R1/R5 verbatim, ~7.1 TB/s measured) ----
    float s0 = 0.f, s1 = 0.f, s2 = 0.f, s3 = 0.f;
    long long idx    = (long long)blockIdx.x * blockDim.x + threadIdx.x;
    long long stride = (long long)gridDim.x * blockDim.x;

    for (long long i = idx; i < n4; i += stride) {
        float4 v = in[i];
        s0 = fmaf(v.x, v.x, s0);
        s1 = fmaf(v.y, v.y, s1);
        s2 = fmaf(v.z, v.z, s2);
        s3 = fmaf(v.w, v.w, s3);
    }
    float s = (s0 + s1) + (s2 + s3);

    #pragma unroll
    for (int o = 16; o > 0; o >>= 1)
        s += __shfl_xor_sync(0xffffffffu, s, o);

    if (lane == 0) ws[wid] = s;
    __syncthreads();

    if (wid == 0) {
        s = (lane < NTHREADS / 32) ? ws[lane] : 0.f;
        #pragma unroll
        for (int o = 16; o > 0; o >>= 1)
            s += __shfl_xor_sync(0xffffffffu, s, o);
        if (lane == 0) g_partials[blockIdx.x] = s;   // released by atomic below
    }

    // ---- election: one acq_rel atomic, no fence ----
    if (threadIdx.x == 0) {
        unsigned int ticket;
        asm volatile("atom.add.acq_rel.gpu.u32 %0, [%1], 1;"
                     : "=r"(ticket) : "l"(&g_count) : "memory");
        s_is_last = (ticket == (unsigned int)(gridDim.x - 1));
    }
    __syncthreads();
    if (!s_is_last) return;

    // ---- last block: reduce 592 partials in double (deterministic) ----
    __shared__ double wd[NTHREADS / 32];
    double d = 0.0;
    for (int p = threadIdx.x; p < NBLOCKS; p += NTHREADS)
        d += (double)g_partials[p];

    #pragma unroll
    for (int o = 16; o > 0; o >>= 1)
        d += __shfl_xor_sync(0xffffffffu, d, o);

    if (lane == 0) wd[wid] = d;
    __syncthreads();

    if (wid == 0) {
        d = (lane < NTHREADS / 32) ? wd[lane] : 0.0;
        #pragma unroll
        for (int o = 16; o > 0; o >>= 1)
            d += __shfl_xor_sync(0xffffffffu, d, o);
        if (lane == 0) {
            out[0] = (float)(d * (double)scale);
            g_count = 0;  // reset for graph replay
        }
    }
}

extern "C" void kernel_launch(void* const* d_in, const int* in_sizes, int n_in,
                              void* d_out, int out_size)
{
    const float* x = (const float*)d_in[0];
    long long n = (long long)in_sizes[0];     // 134217728, divisible by 4
    long long n4 = n >> 2;

    // B*C = n / (256*256) = 2048
    float scale = 1.0f / (float)(n / (256LL * 256LL));

    sqsum_fused_kernel<<<NBLOCKS, NTHREADS>>>((const float4*)x, n4,
                                              (float*)d_out, scale);
}

// round 7
// speedup vs baseline: 1.0835x; 1.0004x over previous
#include <cuda_runtime.h>
#include <cuda_bf16.h>

// NuclearLossFunc: loss = sum(x^2) / (B*C), x: (32,64,256,256) fp32
// = 134,217,728 elements = 512 MiB read. HBM-bound reduction.
//
// R7: DRAM-active time is ~68.2us in every prior variant (7.87 TB/s when
// busy); all remaining time is idle = ramp + CTA finish spread + tail.
// Fix: CTA-level work stealing. 32KB chunks from an atomic counter;
// straggle bound = 1 chunk (~2.4us) instead of static spread (~7us).
// Chunk-id prefetch via 3-slot rotating smem buffer, 1 barrier/chunk.
// Determinism: fixed tree within chunk; chunk sums -> per-thread double
// (reorder noise ~1e-15, float output stable); fixed final tree.

#define NBLOCKS  592            // 148 SMs * 4 CTAs
#define NTHREADS 512
#define CHUNK_F4 2048           // 512 thr * 4 float4 = 32KB per chunk

__device__ double       g_partials[NBLOCKS];
__device__ int          g_work = NBLOCKS;   // next chunk to steal
__device__ unsigned int g_count;            // ticket, zero-init

__global__ __launch_bounds__(NTHREADS) void sqsum_ws_kernel(
    const float4* __restrict__ in, int nchunks,
    float* __restrict__ out, float scale)
{
    const int tid  = threadIdx.x;
    const int lane = tid & 31;
    const int wid  = tid >> 5;
    __shared__ int  s_next[3];
    __shared__ bool s_is_last;

    double acc = 0.0;
    int cur = blockIdx.x;    // chunks 0..591 statically seeded
    int k = 0;

    while (cur < nchunks) {
        long long base = (long long)cur * CHUNK_F4 + tid;
        // issue all 4 loads up front (coalesced, 32B-apart streams share pages)
        float4 a = in[base];
        float4 b = in[base +  512];
        float4 c = in[base + 1024];
        float4 d = in[base + 1536];

        // steal next chunk while loads are in flight
        if (tid == 0) s_next[(k + 1) % 3] = atomicAdd(&g_work, 1);

        float s0 = fmaf(a.x, a.x, a.y * a.y);
        float s1 = fmaf(a.z, a.z, a.w * a.w);
        float s2 = fmaf(b.x, b.x, b.y * b.y);
        float s3 = fmaf(b.z, b.z, b.w * b.w);
        s0 = fmaf(c.x, c.x, s0);  s1 = fmaf(c.y, c.y, s1);
        s2 = fmaf(c.z, c.z, s2);  s3 = fmaf(c.w, c.w, s3);
        s0 = fmaf(d.x, d.x, s0);  s1 = fmaf(d.y, d.y, s1);
        s2 = fmaf(d.z, d.z, s2);  s3 = fmaf(d.w, d.w, s3);
        acc += (double)((s0 + s1) + (s2 + s3));

        __syncthreads();                 // publish s_next[(k+1)%3]
        cur = s_next[(k + 1) % 3];       // slot rewritten only at k+3 (2 barriers away)
        k++;
    }

    // ---- block reduce (double, fixed tree) ----
    #pragma unroll
    for (int o = 16; o > 0; o >>= 1)
        acc += __shfl_xor_sync(0xffffffffu, acc, o);

    __shared__ double wd[NTHREADS / 32];
    if (lane == 0) wd[wid] = acc;
    __syncthreads();

    if (wid == 0) {
        acc = (lane < NTHREADS / 32) ? wd[lane] : 0.0;
        #pragma unroll
        for (int o = 16; o > 0; o >>= 1)
            acc += __shfl_xor_sync(0xffffffffu, acc, o);
        if (lane == 0) g_partials[blockIdx.x] = acc;   // released by acq_rel below
    }

    // ---- last-block election ----
    if (tid == 0) {
        unsigned int ticket;
        asm volatile("atom.add.acq_rel.gpu.u32 %0, [%1], 1;"
                     : "=r"(ticket) : "l"(&g_count) : "memory");
        s_is_last = (ticket == (unsigned int)(gridDim.x - 1));
    }
    __syncthreads();
    if (!s_is_last) return;

    // ---- final: reduce 592 doubles, fixed tree ----
    double dsum = 0.0;
    for (int p = tid; p < NBLOCKS; p += NTHREADS)
        dsum += g_partials[p];

    #pragma unroll
    for (int o = 16; o > 0; o >>= 1)
        dsum += __shfl_xor_sync(0xffffffffu, dsum, o);

    if (lane == 0) wd[wid] = dsum;
    __syncthreads();

    if (wid == 0) {
        dsum = (lane < NTHREADS / 32) ? wd[lane] : 0.0;
        #pragma unroll
        for (int o = 16; o > 0; o >>= 1)
            dsum += __shfl_xor_sync(0xffffffffu, dsum, o);
        if (lane == 0) {
            out[0] = (float)(dsum * (double)scale);
            g_work  = NBLOCKS;   // reset steal counter for next graph replay
            g_count = 0;         // reset ticket
        }
    }
}

extern "C" void kernel_launch(void* const* d_in, const int* in_sizes, int n_in,
                              void* d_out, int out_size)
{
    const float* x = (const float*)d_in[0];
    long long n  = (long long)in_sizes[0];    // 134,217,728
    long long n4 = n >> 2;                    // 33,554,432
    int nchunks  = (int)(n4 / CHUNK_F4);      // 16,384 (exact)

    // B*C = n / (256*256) = 2048
    float scale = 1.0f / (float)(n / (256LL * 256LL));

    sqsum_ws_kernel<<<NBLOCKS, NTHREADS>>>((const float4*)x, nchunks,
                                           (float*)d_out, scale);
}